// round 9
// baseline (speedup 1.0000x reference)
#include <cuda_runtime.h>
#include <cuda_fp16.h>
#include <cstdint>

#define NB 16
#define NC 64          // C_IN == C_OUT == 64
#define VIN 40962
#define VOUT 163842
#define G1X 321        // ceil(VIN/128)
#define G2X 2561       // ceil(VOUT/64)

// Scratch: y[b][u][o] in fp16, rows of 128B. 84 MB (mostly L2-resident).
__device__ __half g_y[(size_t)NB * VIN * NC];
// 1 if idx buffer is int64, 0 if int32.
__device__ int g_idx_is64;

// Side stream + events, created once at static-init (before harness mem
// checkpoints; no device-memory allocation involved).
static cudaStream_t g_s2;
static cudaEvent_t  g_ev[NB];
static cudaEvent_t  g_evEnd;
namespace {
struct InitOnce {
    InitOnce() {
        cudaStreamCreateWithFlags(&g_s2, cudaStreamNonBlocking);
        for (int i = 0; i < NB; i++)
            cudaEventCreateWithFlags(&g_ev[i], cudaEventDisableTiming);
        cudaEventCreateWithFlags(&g_evEnd, cudaEventDisableTiming);
    }
};
static InitOnce s_init;
}

static __device__ __forceinline__ uint32_t pack_h2(float a, float b) {
    __half2 h = __floats2half2_rn(a, b);
    return *(uint32_t*)&h;
}

static __device__ __forceinline__ void mma16816(float* d, const uint32_t* a,
                                                uint32_t b0, uint32_t b1) {
    asm volatile(
        "mma.sync.aligned.m16n8k16.row.col.f32.f16.f16.f32 "
        "{%0,%1,%2,%3}, {%4,%5,%6,%7}, {%8,%9}, {%0,%1,%2,%3};"
        : "+f"(d[0]), "+f"(d[1]), "+f"(d[2]), "+f"(d[3])
        : "r"(a[0]), "r"(a[1]), "r"(a[2]), "r"(a[3]), "r"(b0), "r"(b1));
}

// ---------------------------------------------------------------------------
// Stage 1: y[b,u,o] = sum_c x[b,c,u] W[o,c]  (HMMA m16n8k16, f32 acc, fp16 y)
// One batch per launch (grid.x = 321).
// ---------------------------------------------------------------------------
__global__ __launch_bounds__(128)
void stage1_mma(int b, const float* __restrict__ x, const float* __restrict__ W,
                const void* __restrict__ idx_raw) {
    __shared__ uint32_t xs[128][33];
    __shared__ uint32_t wb[64][33];

    const int u0  = blockIdx.x * 128;
    const int tid = threadIdx.x;

    if (b == 0 && blockIdx.x == 0 && tid == 0) {
        const int* p = (const int*)idx_raw;
        int all_odd_zero = 1;
#pragma unroll
        for (int k = 0; k < 8; k++)
            if (p[2 * k + 1] != 0) all_odd_zero = 0;
        g_idx_is64 = all_odd_zero;
    }

    for (int i = tid; i < 64 * 32; i += 128) {
        int o = i >> 5, cp = i & 31;
        float2 wv = *(const float2*)&W[o * 64 + cp * 2];
        wb[o][cp] = pack_h2(wv.x, wv.y);
    }

    const float* xb = x + (size_t)b * NC * VIN + u0;
    if (u0 + 128 <= VIN) {
#pragma unroll
        for (int i = tid; i < 32 * 64; i += 128) {
            int cp = i >> 6, up = i & 63;
            const float* p0 = xb + (size_t)(2 * cp) * VIN;
            float2 v0 = __ldcs((const float2*)(p0 + 2 * up));
            float2 v1 = __ldcs((const float2*)(p0 + VIN + 2 * up));
            xs[2 * up][cp]     = pack_h2(v0.x, v1.x);
            xs[2 * up + 1][cp] = pack_h2(v0.y, v1.y);
        }
    } else {
        for (int i = tid; i < 32 * 64; i += 128) {
            int cp = i >> 6, up = i & 63;
            const float* p0 = xb + (size_t)(2 * cp) * VIN;
            int uA = 2 * up, uB = 2 * up + 1;
            float a0 = (u0 + uA < VIN) ? p0[uA] : 0.0f;
            float a1 = (u0 + uA < VIN) ? p0[VIN + uA] : 0.0f;
            float b0 = (u0 + uB < VIN) ? p0[uB] : 0.0f;
            float b1 = (u0 + uB < VIN) ? p0[VIN + uB] : 0.0f;
            xs[uA][cp] = pack_h2(a0, a1);
            xs[uB][cp] = pack_h2(b0, b1);
        }
    }
    __syncthreads();

    const int lane = tid & 31, wid = tid >> 5;
    const int g = lane >> 2, t = lane & 3;
    const int ub = wid * 32;

    float acc[2][8][4];
#pragma unroll
    for (int mt = 0; mt < 2; mt++)
#pragma unroll
        for (int nt = 0; nt < 8; nt++)
#pragma unroll
            for (int r = 0; r < 4; r++) acc[mt][nt][r] = 0.0f;

#pragma unroll
    for (int kt = 0; kt < 4; kt++) {
        uint32_t a[2][4];
#pragma unroll
        for (int mt = 0; mt < 2; mt++) {
            int r = ub + mt * 16;
            a[mt][0] = xs[r + g][kt * 8 + t];
            a[mt][1] = xs[r + 8 + g][kt * 8 + t];
            a[mt][2] = xs[r + g][kt * 8 + 4 + t];
            a[mt][3] = xs[r + 8 + g][kt * 8 + 4 + t];
        }
#pragma unroll
        for (int nt = 0; nt < 8; nt++) {
            uint32_t b0 = wb[nt * 8 + g][kt * 8 + t];
            uint32_t b1 = wb[nt * 8 + g][kt * 8 + 4 + t];
            mma16816(acc[0][nt], a[0], b0, b1);
            mma16816(acc[1][nt], a[1], b0, b1);
        }
    }

    __syncthreads();
    uint32_t* ys = (uint32_t*)xs;
#pragma unroll
    for (int mt = 0; mt < 2; mt++) {
        int r0 = ub + mt * 16 + g;
#pragma unroll
        for (int nt = 0; nt < 8; nt++) {
            ys[r0 * 33 + nt * 4 + t]       = pack_h2(acc[mt][nt][0], acc[mt][nt][1]);
            ys[(r0 + 8) * 33 + nt * 4 + t] = pack_h2(acc[mt][nt][2], acc[mt][nt][3]);
        }
    }
    __syncthreads();

    __half* yb = g_y + (size_t)b * VIN * NC;
#pragma unroll
    for (int i = tid; i < 128 * 8; i += 128) {
        int u = i >> 3, q = i & 7;
        if (u0 + u < VIN) {
            const uint32_t* row = ys + u * 33 + q * 4;
            uint4 v = make_uint4(row[0], row[1], row[2], row[3]);
            *(uint4*)&yb[(size_t)(u0 + u) * NC + q * 8] = v;
        }
    }
}

// ---------------------------------------------------------------------------
// Stage 2 (R7 version): out[b,o,v] = 0.5*(y[i0]+y[i1]) + bias[o]
// One batch per launch (grid.x = 2561).
// ---------------------------------------------------------------------------
__global__ __launch_bounds__(256)
void stage2_gather(int b, const void* __restrict__ idx_raw,
                   const float* __restrict__ bias,
                   float* __restrict__ out) {
    __shared__ float t[64][65];
    __shared__ float bs[64];

    const int v0   = blockIdx.x * 64;
    const int tid  = threadIdx.x;
    const int lane = tid & 31;
    const int w    = tid >> 5;
    const int is64 = g_idx_is64;

    if (tid < 64) bs[tid] = bias[tid];

    const __half* yb = g_y + (size_t)b * VIN * NC;

    const int g = lane >> 3;      // vertex within quad
    const int s = lane & 7;       // 16B chunk within 128B row
#pragma unroll
    for (int it = 0; it < 2; it++) {
        const int vl = w * 8 + it * 4 + g;
        const int v  = v0 + vl;
        if (v < VOUT) {
            long long i0, i1;
            if (is64) {
                longlong2 p = *((const longlong2*)idx_raw + v);
                i0 = p.x; i1 = p.y;
            } else {
                int2 p = *((const int2*)idx_raw + v);
                i0 = p.x; i1 = p.y;
            }
            i0 = i0 < 0 ? 0 : (i0 >= VIN ? VIN - 1 : i0);
            i1 = i1 < 0 ? 0 : (i1 >= VIN ? VIN - 1 : i1);
            union { uint4 u; __half2 h[4]; } A, B;
            A.u = *(const uint4*)(yb + (size_t)i0 * NC + s * 8);
            B.u = *(const uint4*)(yb + (size_t)i1 * NC + s * 8);
            float* trow = &t[vl][s * 8];
#pragma unroll
            for (int k = 0; k < 4; k++) {
                float2 fa = __half22float2(A.h[k]);
                float2 fb = __half22float2(B.h[k]);
                trow[2 * k + 0] = 0.5f * (fa.x + fb.x);
                trow[2 * k + 1] = 0.5f * (fa.y + fb.y);
            }
        }
    }
    __syncthreads();

    {
        const int vg = v0 + 2 * lane;
        if (vg < VOUT) {
            float* ob = out + (size_t)b * NC * VOUT + vg;
#pragma unroll
            for (int j = 0; j < 8; j++) {
                const int o = w + 8 * j;
                const float bo = bs[o];
                float2 r = make_float2(t[2 * lane][o] + bo,
                                       t[2 * lane + 1][o] + bo);
                __stcs((float2*)(ob + (size_t)o * VOUT), r);
            }
        }
    }
}

// ---------------------------------------------------------------------------
extern "C" void kernel_launch(void* const* d_in, const int* in_sizes, int n_in,
                              void* d_out, int out_size) {
    const float* x = nullptr;
    const void*  idx = nullptr;
    const float* W = nullptr;
    const float* bias = nullptr;
    for (int i = 0; i < n_in; i++) {
        switch (in_sizes[i]) {
            case 41945088: x    = (const float*)d_in[i]; break;  // 16*64*40962
            case 327684:   idx  = d_in[i];               break;  // 163842*2
            case 4096:     W    = (const float*)d_in[i]; break;  // 64*64
            case 64:       bias = (const float*)d_in[i]; break;  // 64
            default: break;
        }
    }
    float* out = (float*)d_out;
    (void)out_size;

    // Pipelined DAG: main stream runs stage1(b) serially; side stream runs
    // stage2(b) gated on stage1(b)'s event. y slices are per-batch disjoint,
    // so the only dependency is s1(b) -> s2(b). Joined back at the end.
    for (int b = 0; b < NB; b++) {
        stage1_mma<<<G1X, 128>>>(b, x, W, idx);
        cudaEventRecord(g_ev[b], 0);
        cudaStreamWaitEvent(g_s2, g_ev[b], 0);
        stage2_gather<<<G2X, 256, 0, g_s2>>>(b, idx, bias, out);
    }
    cudaEventRecord(g_evEnd, g_s2);
    cudaStreamWaitEvent(0, g_evEnd, 0);
}

// round 10
// speedup vs baseline: 1.2496x; 1.2496x over previous
#include <cuda_runtime.h>
#include <cuda_fp16.h>
#include <cstdint>

#define NB 16
#define NC 64          // C_IN == C_OUT == 64
#define VIN 40962
#define VOUT 163842
#define G1X 321        // ceil(VIN/128)
#define G2X 2561       // ceil(VOUT/64)
#define NGRP 8         // super-groups
#define GB 2           // batches per group

// Scratch: y[b][u][o] in fp16, rows of 128B. 84 MB (mostly L2-resident).
__device__ __half g_y[(size_t)NB * VIN * NC];
// 1 if idx buffer is int64, 0 if int32.
__device__ int g_idx_is64;

// Explicit streams + events (static init; no tracked device memory).
static cudaStream_t g_sA, g_sB;
static cudaEvent_t  g_evFork, g_evA[NGRP], g_evJA, g_evJB;
namespace {
struct InitOnce {
    InitOnce() {
        cudaStreamCreateWithFlags(&g_sA, cudaStreamNonBlocking);
        cudaStreamCreateWithFlags(&g_sB, cudaStreamNonBlocking);
        cudaEventCreateWithFlags(&g_evFork, cudaEventDisableTiming);
        for (int i = 0; i < NGRP; i++)
            cudaEventCreateWithFlags(&g_evA[i], cudaEventDisableTiming);
        cudaEventCreateWithFlags(&g_evJA, cudaEventDisableTiming);
        cudaEventCreateWithFlags(&g_evJB, cudaEventDisableTiming);
    }
};
static InitOnce s_init;
}

static __device__ __forceinline__ uint32_t pack_h2(float a, float b) {
    __half2 h = __floats2half2_rn(a, b);
    return *(uint32_t*)&h;
}

static __device__ __forceinline__ void mma16816(float* d, const uint32_t* a,
                                                uint32_t b0, uint32_t b1) {
    asm volatile(
        "mma.sync.aligned.m16n8k16.row.col.f32.f16.f16.f32 "
        "{%0,%1,%2,%3}, {%4,%5,%6,%7}, {%8,%9}, {%0,%1,%2,%3};"
        : "+f"(d[0]), "+f"(d[1]), "+f"(d[2]), "+f"(d[3])
        : "r"(a[0]), "r"(a[1]), "r"(a[2]), "r"(a[3]), "r"(b0), "r"(b1));
}

// ---------------------------------------------------------------------------
// Stage 1 (R7-exact, batch-base param): y = x^T W^T via HMMA, fp16 y.
// grid = (321, GB); b = b0 + blockIdx.y.
// ---------------------------------------------------------------------------
__global__ __launch_bounds__(128)
void stage1_mma(int b0, const float* __restrict__ x, const float* __restrict__ W,
                const void* __restrict__ idx_raw) {
    __shared__ uint32_t xs[128][33];
    __shared__ uint32_t wb[64][33];

    const int b   = b0 + blockIdx.y;
    const int u0  = blockIdx.x * 128;
    const int tid = threadIdx.x;

    if (b == 0 && blockIdx.x == 0 && tid == 0) {
        const int* p = (const int*)idx_raw;
        int all_odd_zero = 1;
#pragma unroll
        for (int k = 0; k < 8; k++)
            if (p[2 * k + 1] != 0) all_odd_zero = 0;
        g_idx_is64 = all_odd_zero;
    }

    for (int i = tid; i < 64 * 32; i += 128) {
        int o = i >> 5, cp = i & 31;
        float2 wv = *(const float2*)&W[o * 64 + cp * 2];
        wb[o][cp] = pack_h2(wv.x, wv.y);
    }

    const float* xb = x + (size_t)b * NC * VIN + u0;
    if (u0 + 128 <= VIN) {
#pragma unroll
        for (int i = tid; i < 32 * 64; i += 128) {
            int cp = i >> 6, up = i & 63;
            const float* p0 = xb + (size_t)(2 * cp) * VIN;
            float2 v0 = __ldcs((const float2*)(p0 + 2 * up));
            float2 v1 = __ldcs((const float2*)(p0 + VIN + 2 * up));
            xs[2 * up][cp]     = pack_h2(v0.x, v1.x);
            xs[2 * up + 1][cp] = pack_h2(v0.y, v1.y);
        }
    } else {
        for (int i = tid; i < 32 * 64; i += 128) {
            int cp = i >> 6, up = i & 63;
            const float* p0 = xb + (size_t)(2 * cp) * VIN;
            int uA = 2 * up, uB = 2 * up + 1;
            float a0 = (u0 + uA < VIN) ? p0[uA] : 0.0f;
            float a1 = (u0 + uA < VIN) ? p0[VIN + uA] : 0.0f;
            float b0f = (u0 + uB < VIN) ? p0[uB] : 0.0f;
            float b1f = (u0 + uB < VIN) ? p0[VIN + uB] : 0.0f;
            xs[uA][cp] = pack_h2(a0, a1);
            xs[uB][cp] = pack_h2(b0f, b1f);
        }
    }
    __syncthreads();

    const int lane = tid & 31, wid = tid >> 5;
    const int g = lane >> 2, t = lane & 3;
    const int ub = wid * 32;

    float acc[2][8][4];
#pragma unroll
    for (int mt = 0; mt < 2; mt++)
#pragma unroll
        for (int nt = 0; nt < 8; nt++)
#pragma unroll
            for (int r = 0; r < 4; r++) acc[mt][nt][r] = 0.0f;

#pragma unroll
    for (int kt = 0; kt < 4; kt++) {
        uint32_t a[2][4];
#pragma unroll
        for (int mt = 0; mt < 2; mt++) {
            int r = ub + mt * 16;
            a[mt][0] = xs[r + g][kt * 8 + t];
            a[mt][1] = xs[r + 8 + g][kt * 8 + t];
            a[mt][2] = xs[r + g][kt * 8 + 4 + t];
            a[mt][3] = xs[r + 8 + g][kt * 8 + 4 + t];
        }
#pragma unroll
        for (int nt = 0; nt < 8; nt++) {
            uint32_t b0r = wb[nt * 8 + g][kt * 8 + t];
            uint32_t b1r = wb[nt * 8 + g][kt * 8 + 4 + t];
            mma16816(acc[0][nt], a[0], b0r, b1r);
            mma16816(acc[1][nt], a[1], b0r, b1r);
        }
    }

    __syncthreads();
    uint32_t* ys = (uint32_t*)xs;
#pragma unroll
    for (int mt = 0; mt < 2; mt++) {
        int r0 = ub + mt * 16 + g;
#pragma unroll
        for (int nt = 0; nt < 8; nt++) {
            ys[r0 * 33 + nt * 4 + t]       = pack_h2(acc[mt][nt][0], acc[mt][nt][1]);
            ys[(r0 + 8) * 33 + nt * 4 + t] = pack_h2(acc[mt][nt][2], acc[mt][nt][3]);
        }
    }
    __syncthreads();

    __half* yb = g_y + (size_t)b * VIN * NC;
#pragma unroll
    for (int i = tid; i < 128 * 8; i += 128) {
        int u = i >> 3, q = i & 7;
        if (u0 + u < VIN) {
            const uint32_t* row = ys + u * 33 + q * 4;
            uint4 v = make_uint4(row[0], row[1], row[2], row[3]);
            *(uint4*)&yb[(size_t)(u0 + u) * NC + q * 8] = v;
        }
    }
}

// ---------------------------------------------------------------------------
// Stage 2 (R7-exact, batch-base param). grid = (2561, GB); b = b0+blockIdx.y.
// ---------------------------------------------------------------------------
__global__ __launch_bounds__(256)
void stage2_gather(int b0, const void* __restrict__ idx_raw,
                   const float* __restrict__ bias,
                   float* __restrict__ out) {
    __shared__ float t[64][65];
    __shared__ float bs[64];

    const int b    = b0 + blockIdx.y;
    const int v0   = blockIdx.x * 64;
    const int tid  = threadIdx.x;
    const int lane = tid & 31;
    const int w    = tid >> 5;
    const int is64 = g_idx_is64;

    if (tid < 64) bs[tid] = bias[tid];

    const __half* yb = g_y + (size_t)b * VIN * NC;

    const int g = lane >> 3;
    const int s = lane & 7;
#pragma unroll
    for (int it = 0; it < 2; it++) {
        const int vl = w * 8 + it * 4 + g;
        const int v  = v0 + vl;
        if (v < VOUT) {
            long long i0, i1;
            if (is64) {
                longlong2 p = *((const longlong2*)idx_raw + v);
                i0 = p.x; i1 = p.y;
            } else {
                int2 p = *((const int2*)idx_raw + v);
                i0 = p.x; i1 = p.y;
            }
            i0 = i0 < 0 ? 0 : (i0 >= VIN ? VIN - 1 : i0);
            i1 = i1 < 0 ? 0 : (i1 >= VIN ? VIN - 1 : i1);
            union { uint4 u; __half2 h[4]; } A, B;
            A.u = *(const uint4*)(yb + (size_t)i0 * NC + s * 8);
            B.u = *(const uint4*)(yb + (size_t)i1 * NC + s * 8);
            float* trow = &t[vl][s * 8];
#pragma unroll
            for (int k = 0; k < 4; k++) {
                float2 fa = __half22float2(A.h[k]);
                float2 fb = __half22float2(B.h[k]);
                trow[2 * k + 0] = 0.5f * (fa.x + fb.x);
                trow[2 * k + 1] = 0.5f * (fa.y + fb.y);
            }
        }
    }
    __syncthreads();

    {
        const int vg = v0 + 2 * lane;
        if (vg < VOUT) {
            float* ob = out + (size_t)b * NC * VOUT + vg;
#pragma unroll
            for (int j = 0; j < 8; j++) {
                const int o = w + 8 * j;
                const float bo = bs[o];
                float2 r = make_float2(t[2 * lane][o] + bo,
                                       t[2 * lane + 1][o] + bo);
                __stcs((float2*)(ob + (size_t)o * VOUT), r);
            }
        }
    }
}

// ---------------------------------------------------------------------------
extern "C" void kernel_launch(void* const* d_in, const int* in_sizes, int n_in,
                              void* d_out, int out_size) {
    const float* x = nullptr;
    const void*  idx = nullptr;
    const float* W = nullptr;
    const float* bias = nullptr;
    for (int i = 0; i < n_in; i++) {
        switch (in_sizes[i]) {
            case 41945088: x    = (const float*)d_in[i]; break;  // 16*64*40962
            case 327684:   idx  = d_in[i];               break;  // 163842*2
            case 4096:     W    = (const float*)d_in[i]; break;  // 64*64
            case 64:       bias = (const float*)d_in[i]; break;  // 64
            default: break;
        }
    }
    float* out = (float*)d_out;
    (void)out_size;

    // Fork both explicit streams off the capture (default) stream. All real
    // work happens on g_sA / g_sB so legacy-stream implicit sync never bites.
    cudaEventRecord(g_evFork, 0);
    cudaStreamWaitEvent(g_sA, g_evFork, 0);
    cudaStreamWaitEvent(g_sB, g_evFork, 0);

    for (int g = 0; g < NGRP; g++) {
        const int b0 = g * GB;
        stage1_mma<<<dim3(G1X, GB), 128, 0, g_sA>>>(b0, x, W, idx);
        cudaEventRecord(g_evA[g], g_sA);
        cudaStreamWaitEvent(g_sB, g_evA[g], 0);
        stage2_gather<<<dim3(G2X, GB), 256, 0, g_sB>>>(b0, idx, bias, out);
    }

    // Join both streams back to the capture stream.
    cudaEventRecord(g_evJA, g_sA);
    cudaEventRecord(g_evJB, g_sB);
    cudaStreamWaitEvent(0, g_evJA, 0);
    cudaStreamWaitEvent(0, g_evJB, 0);
}

// round 11
// speedup vs baseline: 1.5701x; 1.2565x over previous
#include <cuda_runtime.h>
#include <cuda_fp16.h>
#include <cstdint>

#define NB 16
#define NC 64          // C_IN == C_OUT == 64
#define VIN 40962
#define VOUT 163842

// Scratch: y[b][u][o] in fp16, rows of 128B. 84 MB.
__device__ __half g_y[(size_t)NB * VIN * NC];
// 1 if idx buffer is int64, 0 if int32.
__device__ int g_idx_is64;

static __device__ __forceinline__ uint32_t pack_h2(float a, float b) {
    __half2 h = __floats2half2_rn(a, b);
    return *(uint32_t*)&h;
}

static __device__ __forceinline__ void mma16816(float* d, const uint32_t* a,
                                                uint32_t b0, uint32_t b1) {
    asm volatile(
        "mma.sync.aligned.m16n8k16.row.col.f32.f16.f16.f32 "
        "{%0,%1,%2,%3}, {%4,%5,%6,%7}, {%8,%9}, {%0,%1,%2,%3};"
        : "+f"(d[0]), "+f"(d[1]), "+f"(d[2]), "+f"(d[3])
        : "r"(a[0]), "r"(a[1]), "r"(a[2]), "r"(a[3]), "r"(b0), "r"(b1));
}

// ---------------------------------------------------------------------------
// Stage 1: y[b,u,o] = sum_c x[b,c,u] W[o,c]  (HMMA m16n8k16, f32 acc, fp16 y)
// 256 threads, tile 128u x 64o; warp w covers u strip [w*16, w*16+16).
// 32 acc regs/thread -> <=64 regs -> 4 blocks/SM -> 50% occupancy.
// ---------------------------------------------------------------------------
__global__ __launch_bounds__(256, 4)
void stage1_mma(const float* __restrict__ x, const float* __restrict__ W,
                const void* __restrict__ idx_raw) {
    __shared__ uint32_t xs[128][33];   // [u][cp] half2(x[2cp][u], x[2cp+1][u])
    __shared__ uint32_t wb[64][33];    // [o][cp] half2(W[o][2cp], W[o][2cp+1])

    const int b   = blockIdx.y;
    const int u0  = blockIdx.x * 128;
    const int tid = threadIdx.x;

    if (b == 0 && blockIdx.x == 0 && tid == 0) {
        const int* p = (const int*)idx_raw;
        int all_odd_zero = 1;
#pragma unroll
        for (int k = 0; k < 8; k++)
            if (p[2 * k + 1] != 0) all_odd_zero = 0;
        g_idx_is64 = all_odd_zero;
    }

#pragma unroll
    for (int i = tid; i < 64 * 32; i += 256) {
        int o = i >> 5, cp = i & 31;
        float2 wv = *(const float2*)&W[o * 64 + cp * 2];
        wb[o][cp] = pack_h2(wv.x, wv.y);
    }

    const float* xb = x + (size_t)b * NC * VIN + u0;
    if (u0 + 128 <= VIN) {
#pragma unroll
        for (int i = tid; i < 32 * 64; i += 256) {
            int cp = i >> 6, up = i & 63;
            const float* p0 = xb + (size_t)(2 * cp) * VIN;
            float2 v0 = __ldcs((const float2*)(p0 + 2 * up));
            float2 v1 = __ldcs((const float2*)(p0 + VIN + 2 * up));
            xs[2 * up][cp]     = pack_h2(v0.x, v1.x);
            xs[2 * up + 1][cp] = pack_h2(v0.y, v1.y);
        }
    } else {
        for (int i = tid; i < 32 * 64; i += 256) {
            int cp = i >> 6, up = i & 63;
            const float* p0 = xb + (size_t)(2 * cp) * VIN;
            int uA = 2 * up, uB = 2 * up + 1;
            float a0 = (u0 + uA < VIN) ? p0[uA] : 0.0f;
            float a1 = (u0 + uA < VIN) ? p0[VIN + uA] : 0.0f;
            float b0f = (u0 + uB < VIN) ? p0[uB] : 0.0f;
            float b1f = (u0 + uB < VIN) ? p0[VIN + uB] : 0.0f;
            xs[uA][cp] = pack_h2(a0, a1);
            xs[uB][cp] = pack_h2(b0f, b1f);
        }
    }
    __syncthreads();

    const int lane = tid & 31, wid = tid >> 5;   // 8 warps
    const int g = lane >> 2, t = lane & 3;
    const int ub = wid * 16;

    float acc[8][4];
#pragma unroll
    for (int nt = 0; nt < 8; nt++)
#pragma unroll
        for (int r = 0; r < 4; r++) acc[nt][r] = 0.0f;

#pragma unroll
    for (int kt = 0; kt < 4; kt++) {
        uint32_t a[4];
        a[0] = xs[ub + g][kt * 8 + t];
        a[1] = xs[ub + 8 + g][kt * 8 + t];
        a[2] = xs[ub + g][kt * 8 + 4 + t];
        a[3] = xs[ub + 8 + g][kt * 8 + 4 + t];
#pragma unroll
        for (int nt = 0; nt < 8; nt++) {
            uint32_t b0 = wb[nt * 8 + g][kt * 8 + t];
            uint32_t b1 = wb[nt * 8 + g][kt * 8 + 4 + t];
            mma16816(acc[nt], a, b0, b1);
        }
    }

    __syncthreads();
    uint32_t* ys = (uint32_t*)xs;   // [u][32 half2 words], stride 33
    {
        int r0 = ub + g;
#pragma unroll
        for (int nt = 0; nt < 8; nt++) {
            ys[r0 * 33 + nt * 4 + t]       = pack_h2(acc[nt][0], acc[nt][1]);
            ys[(r0 + 8) * 33 + nt * 4 + t] = pack_h2(acc[nt][2], acc[nt][3]);
        }
    }
    __syncthreads();

    __half* yb = g_y + (size_t)b * VIN * NC;
#pragma unroll
    for (int i = tid; i < 128 * 8; i += 256) {
        int u = i >> 3, q = i & 7;
        if (u0 + u < VIN) {
            const uint32_t* row = ys + u * 33 + q * 4;
            uint4 v = make_uint4(row[0], row[1], row[2], row[3]);
            *(uint4*)&yb[(size_t)(u0 + u) * NC + q * 8] = v;
        }
    }
}

// ---------------------------------------------------------------------------
// Stage 2: out[b,o,v] = 0.5*(y[i0]+y[i1]) + bias[o]
// Gather: R7 scheme (8 lanes x 16B = full 128B y-row per LDG.128).
// Write: lane = v mapping -> bank-conflict-free LDS, coalesced STG.32.
// ---------------------------------------------------------------------------
__global__ __launch_bounds__(256)
void stage2_gather(const void* __restrict__ idx_raw,
                   const float* __restrict__ bias,
                   float* __restrict__ out) {
    __shared__ float t[64][65];
    __shared__ float bs[64];

    const int b    = blockIdx.y;
    const int v0   = blockIdx.x * 64;
    const int tid  = threadIdx.x;
    const int lane = tid & 31;
    const int w    = tid >> 5;
    const int is64 = g_idx_is64;

    if (tid < 64) bs[tid] = bias[tid];

    const __half* yb = g_y + (size_t)b * VIN * NC;

    const int g = lane >> 3;      // vertex within quad
    const int s = lane & 7;       // 16B chunk within 128B row
#pragma unroll
    for (int it = 0; it < 2; it++) {
        const int vl = w * 8 + it * 4 + g;
        const int v  = v0 + vl;
        if (v < VOUT) {
            long long i0, i1;
            if (is64) {
                longlong2 p = *((const longlong2*)idx_raw + v);
                i0 = p.x; i1 = p.y;
            } else {
                int2 p = *((const int2*)idx_raw + v);
                i0 = p.x; i1 = p.y;
            }
            i0 = i0 < 0 ? 0 : (i0 >= VIN ? VIN - 1 : i0);
            i1 = i1 < 0 ? 0 : (i1 >= VIN ? VIN - 1 : i1);
            union { uint4 u; __half2 h[4]; } A, B;
            A.u = *(const uint4*)(yb + (size_t)i0 * NC + s * 8);
            B.u = *(const uint4*)(yb + (size_t)i1 * NC + s * 8);
            float* trow = &t[vl][s * 8];
#pragma unroll
            for (int k = 0; k < 4; k++) {
                float2 fa = __half22float2(A.h[k]);
                float2 fb = __half22float2(B.h[k]);
                trow[2 * k + 0] = 0.5f * (fa.x + fb.x);
                trow[2 * k + 1] = 0.5f * (fa.y + fb.y);
            }
        }
    }
    __syncthreads();

    // Write: warp w -> 8 o-rows; lane = v (conflict-free LDS, coalesced STG).
    {
        const int vA = v0 + lane;
        const int vB = vA + 32;
        float* ob = out + (size_t)b * NC * VOUT;
#pragma unroll
        for (int j = 0; j < 8; j++) {
            const int o  = w * 8 + j;
            const float bo = bs[o];
            float* orow = ob + (size_t)o * VOUT;
            if (vA < VOUT) __stcs(orow + vA, t[lane][o] + bo);
            if (vB < VOUT) __stcs(orow + vB, t[lane + 32][o] + bo);
        }
    }
}

// ---------------------------------------------------------------------------
extern "C" void kernel_launch(void* const* d_in, const int* in_sizes, int n_in,
                              void* d_out, int out_size) {
    const float* x = nullptr;
    const void*  idx = nullptr;
    const float* W = nullptr;
    const float* bias = nullptr;
    for (int i = 0; i < n_in; i++) {
        switch (in_sizes[i]) {
            case 41945088: x    = (const float*)d_in[i]; break;  // 16*64*40962
            case 327684:   idx  = d_in[i];               break;  // 163842*2
            case 4096:     W    = (const float*)d_in[i]; break;  // 64*64
            case 64:       bias = (const float*)d_in[i]; break;  // 64
            default: break;
        }
    }
    float* out = (float*)d_out;
    (void)out_size;

    dim3 g1((VIN + 127) / 128, NB);
    stage1_mma<<<g1, 256>>>(x, W, idx);

    dim3 g2((VOUT + 63) / 64, NB);
    stage2_gather<<<g2, 256>>>(idx, bias, out);
}

// round 12
// speedup vs baseline: 1.7362x; 1.1058x over previous
#include <cuda_runtime.h>
#include <cuda_fp16.h>
#include <cstdint>

#define NB 16
#define NC 64          // C_IN == C_OUT == 64
#define VIN 40962
#define VOUT 163842

// Scratch: y[b][u][o] in fp16, rows of 128B. 84 MB.
__device__ __half g_y[(size_t)NB * VIN * NC];
// 1 if idx buffer is int64, 0 if int32.
__device__ int g_idx_is64;

static __device__ __forceinline__ uint32_t pack_h2(float a, float b) {
    __half2 h = __floats2half2_rn(a, b);
    return *(uint32_t*)&h;
}

static __device__ __forceinline__ void mma16816(float* d, const uint32_t* a,
                                                uint32_t b0, uint32_t b1) {
    asm volatile(
        "mma.sync.aligned.m16n8k16.row.col.f32.f16.f16.f32 "
        "{%0,%1,%2,%3}, {%4,%5,%6,%7}, {%8,%9}, {%0,%1,%2,%3};"
        : "+f"(d[0]), "+f"(d[1]), "+f"(d[2]), "+f"(d[3])
        : "r"(a[0]), "r"(a[1]), "r"(a[2]), "r"(a[3]), "r"(b0), "r"(b1));
}

// ---------------------------------------------------------------------------
// Stage 1: y[b,u,o] = sum_c x[b,c,u] W[o,c]  (HMMA m16n8k16, f32 acc, fp16 y)
// 256 threads, tile 128u x 64o; warp w covers u strip [w*16, w*16+16).
// W staged in FRAGMENT layout (wbf): mainloop B loads are conflict-free
// LDS.64 -> mainloop smem wavefronts drop ~2.5x vs row-major wb.
// ---------------------------------------------------------------------------
__global__ __launch_bounds__(256, 4)
void stage1_mma(const float* __restrict__ x, const float* __restrict__ W,
                const void* __restrict__ idx_raw) {
    __shared__ uint32_t xs[128][33];     // [u][cp] half2(x[2cp][u], x[2cp+1][u])
    __shared__ uint2    wbf[8][4][32];   // [nt][kt][lane] = {b0, b1}  (8 KB)

    const int b   = blockIdx.y;
    const int u0  = blockIdx.x * 128;
    const int tid = threadIdx.x;

    if (b == 0 && blockIdx.x == 0 && tid == 0) {
        const int* p = (const int*)idx_raw;
        int all_odd_zero = 1;
#pragma unroll
        for (int k = 0; k < 8; k++)
            if (p[2 * k + 1] != 0) all_odd_zero = 0;
        g_idx_is64 = all_odd_zero;
    }

    // ---- W fragments: wbf[nt][kt][lane] = { wb[nt*8+g][kt*8+t], wb[..][kt*8+4+t] }
    // where wb[o][cp] = half2(W[o][2cp], W[o][2cp+1]); g = lane>>2, t = lane&3.
#pragma unroll
    for (int i = tid; i < 8 * 4 * 32; i += 256) {
        const int nt = i >> 7, kt = (i >> 5) & 3, ln = i & 31;
        const int o   = nt * 8 + (ln >> 2);
        const int cp0 = kt * 8 + (ln & 3);
        float2 wlo = *(const float2*)&W[o * 64 + cp0 * 2];
        float2 whi = *(const float2*)&W[o * 64 + (cp0 + 4) * 2];
        wbf[nt][kt][ln] = make_uint2(pack_h2(wlo.x, wlo.y), pack_h2(whi.x, whi.y));
    }

    // ---- x tile fill (unchanged) ----
    const float* xb = x + (size_t)b * NC * VIN + u0;
    if (u0 + 128 <= VIN) {
#pragma unroll
        for (int i = tid; i < 32 * 64; i += 256) {
            int cp = i >> 6, up = i & 63;
            const float* p0 = xb + (size_t)(2 * cp) * VIN;
            float2 v0 = __ldcs((const float2*)(p0 + 2 * up));
            float2 v1 = __ldcs((const float2*)(p0 + VIN + 2 * up));
            xs[2 * up][cp]     = pack_h2(v0.x, v1.x);
            xs[2 * up + 1][cp] = pack_h2(v0.y, v1.y);
        }
    } else {
        for (int i = tid; i < 32 * 64; i += 256) {
            int cp = i >> 6, up = i & 63;
            const float* p0 = xb + (size_t)(2 * cp) * VIN;
            int uA = 2 * up, uB = 2 * up + 1;
            float a0 = (u0 + uA < VIN) ? p0[uA] : 0.0f;
            float a1 = (u0 + uA < VIN) ? p0[VIN + uA] : 0.0f;
            float b0f = (u0 + uB < VIN) ? p0[uB] : 0.0f;
            float b1f = (u0 + uB < VIN) ? p0[VIN + uB] : 0.0f;
            xs[uA][cp] = pack_h2(a0, a1);
            xs[uB][cp] = pack_h2(b0f, b1f);
        }
    }
    __syncthreads();

    const int lane = tid & 31, wid = tid >> 5;   // 8 warps
    const int g = lane >> 2, t = lane & 3;
    const int ub = wid * 16;

    float acc[8][4];
#pragma unroll
    for (int nt = 0; nt < 8; nt++)
#pragma unroll
        for (int r = 0; r < 4; r++) acc[nt][r] = 0.0f;

#pragma unroll
    for (int kt = 0; kt < 4; kt++) {
        uint32_t a[4];
        a[0] = xs[ub + g][kt * 8 + t];
        a[1] = xs[ub + 8 + g][kt * 8 + t];
        a[2] = xs[ub + g][kt * 8 + 4 + t];
        a[3] = xs[ub + 8 + g][kt * 8 + 4 + t];
#pragma unroll
        for (int nt = 0; nt < 8; nt++) {
            uint2 bb = wbf[nt][kt][lane];   // conflict-free LDS.64
            mma16816(acc[nt], a, bb.x, bb.y);
        }
    }

    __syncthreads();
    uint32_t* ys = (uint32_t*)xs;   // [u][32 half2 words], stride 33
    {
        int r0 = ub + g;
#pragma unroll
        for (int nt = 0; nt < 8; nt++) {
            ys[r0 * 33 + nt * 4 + t]       = pack_h2(acc[nt][0], acc[nt][1]);
            ys[(r0 + 8) * 33 + nt * 4 + t] = pack_h2(acc[nt][2], acc[nt][3]);
        }
    }
    __syncthreads();

    __half* yb = g_y + (size_t)b * VIN * NC;
#pragma unroll
    for (int i = tid; i < 128 * 8; i += 256) {
        int u = i >> 3, q = i & 7;
        if (u0 + u < VIN) {
            const uint32_t* row = ys + u * 33 + q * 4;
            uint4 v = make_uint4(row[0], row[1], row[2], row[3]);
            *(uint4*)&yb[(size_t)(u0 + u) * NC + q * 8] = v;
        }
    }
}

// ---------------------------------------------------------------------------
// Stage 2 (R11-exact): out[b,o,v] = 0.5*(y[i0]+y[i1]) + bias[o]
// ---------------------------------------------------------------------------
__global__ __launch_bounds__(256)
void stage2_gather(const void* __restrict__ idx_raw,
                   const float* __restrict__ bias,
                   float* __restrict__ out) {
    __shared__ float t[64][65];
    __shared__ float bs[64];

    const int b    = blockIdx.y;
    const int v0   = blockIdx.x * 64;
    const int tid  = threadIdx.x;
    const int lane = tid & 31;
    const int w    = tid >> 5;
    const int is64 = g_idx_is64;

    if (tid < 64) bs[tid] = bias[tid];

    const __half* yb = g_y + (size_t)b * VIN * NC;

    const int g = lane >> 3;      // vertex within quad
    const int s = lane & 7;       // 16B chunk within 128B row
#pragma unroll
    for (int it = 0; it < 2; it++) {
        const int vl = w * 8 + it * 4 + g;
        const int v  = v0 + vl;
        if (v < VOUT) {
            long long i0, i1;
            if (is64) {
                longlong2 p = *((const longlong2*)idx_raw + v);
                i0 = p.x; i1 = p.y;
            } else {
                int2 p = *((const int2*)idx_raw + v);
                i0 = p.x; i1 = p.y;
            }
            i0 = i0 < 0 ? 0 : (i0 >= VIN ? VIN - 1 : i0);
            i1 = i1 < 0 ? 0 : (i1 >= VIN ? VIN - 1 : i1);
            union { uint4 u; __half2 h[4]; } A, B;
            A.u = *(const uint4*)(yb + (size_t)i0 * NC + s * 8);
            B.u = *(const uint4*)(yb + (size_t)i1 * NC + s * 8);
            float* trow = &t[vl][s * 8];
#pragma unroll
            for (int k = 0; k < 4; k++) {
                float2 fa = __half22float2(A.h[k]);
                float2 fb = __half22float2(B.h[k]);
                trow[2 * k + 0] = 0.5f * (fa.x + fb.x);
                trow[2 * k + 1] = 0.5f * (fa.y + fb.y);
            }
        }
    }
    __syncthreads();

    {
        const int vA = v0 + lane;
        const int vB = vA + 32;
        float* ob = out + (size_t)b * NC * VOUT;
#pragma unroll
        for (int j = 0; j < 8; j++) {
            const int o  = w * 8 + j;
            const float bo = bs[o];
            float* orow = ob + (size_t)o * VOUT;
            if (vA < VOUT) __stcs(orow + vA, t[lane][o] + bo);
            if (vB < VOUT) __stcs(orow + vB, t[lane + 32][o] + bo);
        }
    }
}

// ---------------------------------------------------------------------------
extern "C" void kernel_launch(void* const* d_in, const int* in_sizes, int n_in,
                              void* d_out, int out_size) {
    const float* x = nullptr;
    const void*  idx = nullptr;
    const float* W = nullptr;
    const float* bias = nullptr;
    for (int i = 0; i < n_in; i++) {
        switch (in_sizes[i]) {
            case 41945088: x    = (const float*)d_in[i]; break;  // 16*64*40962
            case 327684:   idx  = d_in[i];               break;  // 163842*2
            case 4096:     W    = (const float*)d_in[i]; break;  // 64*64
            case 64:       bias = (const float*)d_in[i]; break;  // 64
            default: break;
        }
    }
    float* out = (float*)d_out;
    (void)out_size;

    dim3 g1((VIN + 127) / 128, NB);
    stage1_mma<<<g1, 256>>>(x, W, idx);

    dim3 g2((VOUT + 63) / 64, NB);
    stage2_gather<<<g2, 256>>>(idx, bias, out);
}